// round 15
// baseline (speedup 1.0000x reference)
#include <cuda_runtime.h>
#include <cstdint>

#define Bc      131072
#define TILE    32
#define NTHREADS 128
// transposed activation layout: hT[k][m], k=0..255, m=0..31 (32 floats/row, swizzled)

typedef unsigned long long ULL;

// ---------------- device scratch (no allocations allowed) ----------------
__device__ float g_W1T[256 * 256];
__device__ float g_W2T[256 * 256];
__device__ float g_W0T[256 * 12];   // [j][k], k padded 11->12

__global__ void transpose_kernel(const float* __restrict__ W0,
                                 const float* __restrict__ W1,
                                 const float* __restrict__ W2) {
    int i = blockIdx.x;      // 0..255 (source row)
    int j = threadIdx.x;     // 0..255 (source col)
    g_W1T[j * 256 + i] = W1[i * 256 + j];
    g_W2T[j * 256 + i] = W2[i * 256 + j];
    if (i < 11)  g_W0T[j * 12 + i] = W0[i * 256 + j];
    if (i == 11) g_W0T[j * 12 + 11] = 0.0f;
}

// accurate-enough tanh: 2 MUFU (EX2 + RCP), abs err ~1e-7
__device__ __forceinline__ float tanh_fast(float x) {
    float xc = fminf(fmaxf(x, -15.0f), 15.0f);
    float e  = __expf(2.0f * xc);
    return __fdividef(e - 1.0f, e + 1.0f);
}

// packed f32x2 helpers
#define FMA2(d, a, b, c) \
    asm("fma.rn.f32x2 %0, %1, %2, %3;" : "=l"(d) : "l"(a), "l"(b), "l"(c))
#define BCAST2(d, s) \
    asm("mov.b64 %0, {%1, %1};" : "=l"(d) : "r"(s))
#define UNPACK2(lo, hi, s) \
    asm("mov.b64 {%0, %1}, %2;" : "=r"(lo), "=r"(hi) : "l"(s))

// swizzle: element (row, m) lives at  row*32 + (m ^ (4*((row>>3)&7)))
__device__ __forceinline__ int swz_f(int row) { return 4 * ((row >> 3) & 7); }

#define M_TANH 0   // hout = tanh(acc + bias)
#define M_D3   1   // h3 = tanh(acc + bias); hout = W3[j] * (1 - h3^2)
#define M_BWD  2   // hout = acc * (1 - hout^2)   (in-place, hout holds forward act)

// 32 FFMA2 for one k-step: row pairs in hA (m0..m0+3) / hB (m0+4..m0+7),
// 8 weight cols in wva (j0..j0+3) / wvb (j0+4..j0+7)
#define KSTEP8(hA, hB, wva, wvb)                                       \
    do {                                                               \
        ULL b0, b1, b2, b3, b4, b5, b6, b7;                            \
        BCAST2(b0, __float_as_uint((wva).x));                          \
        BCAST2(b1, __float_as_uint((wva).y));                          \
        BCAST2(b2, __float_as_uint((wva).z));                          \
        BCAST2(b3, __float_as_uint((wva).w));                          \
        BCAST2(b4, __float_as_uint((wvb).x));                          \
        BCAST2(b5, __float_as_uint((wvb).y));                          \
        BCAST2(b6, __float_as_uint((wvb).z));                          \
        BCAST2(b7, __float_as_uint((wvb).w));                          \
        FMA2(acc2[0][0], (hA).x, b0, acc2[0][0]);                      \
        FMA2(acc2[1][0], (hA).y, b0, acc2[1][0]);                      \
        FMA2(acc2[2][0], (hB).x, b0, acc2[2][0]);                      \
        FMA2(acc2[3][0], (hB).y, b0, acc2[3][0]);                      \
        FMA2(acc2[0][1], (hA).x, b1, acc2[0][1]);                      \
        FMA2(acc2[1][1], (hA).y, b1, acc2[1][1]);                      \
        FMA2(acc2[2][1], (hB).x, b1, acc2[2][1]);                      \
        FMA2(acc2[3][1], (hB).y, b1, acc2[3][1]);                      \
        FMA2(acc2[0][2], (hA).x, b2, acc2[0][2]);                      \
        FMA2(acc2[1][2], (hA).y, b2, acc2[1][2]);                      \
        FMA2(acc2[2][2], (hB).x, b2, acc2[2][2]);                      \
        FMA2(acc2[3][2], (hB).y, b2, acc2[3][2]);                      \
        FMA2(acc2[0][3], (hA).x, b3, acc2[0][3]);                      \
        FMA2(acc2[1][3], (hA).y, b3, acc2[1][3]);                      \
        FMA2(acc2[2][3], (hB).x, b3, acc2[2][3]);                      \
        FMA2(acc2[3][3], (hB).y, b3, acc2[3][3]);                      \
        FMA2(acc2[0][4], (hA).x, b4, acc2[0][4]);                      \
        FMA2(acc2[1][4], (hA).y, b4, acc2[1][4]);                      \
        FMA2(acc2[2][4], (hB).x, b4, acc2[2][4]);                      \
        FMA2(acc2[3][4], (hB).y, b4, acc2[3][4]);                      \
        FMA2(acc2[0][5], (hA).x, b5, acc2[0][5]);                      \
        FMA2(acc2[1][5], (hA).y, b5, acc2[1][5]);                      \
        FMA2(acc2[2][5], (hB).x, b5, acc2[2][5]);                      \
        FMA2(acc2[3][5], (hB).y, b5, acc2[3][5]);                      \
        FMA2(acc2[0][6], (hA).x, b6, acc2[0][6]);                      \
        FMA2(acc2[1][6], (hA).y, b6, acc2[1][6]);                      \
        FMA2(acc2[2][6], (hB).x, b6, acc2[2][6]);                      \
        FMA2(acc2[3][6], (hB).y, b6, acc2[3][6]);                      \
        FMA2(acc2[0][7], (hA).x, b7, acc2[0][7]);                      \
        FMA2(acc2[1][7], (hA).y, b7, acc2[1][7]);                      \
        FMA2(acc2[2][7], (hB).x, b7, acc2[2][7]);                      \
        FMA2(acc2[3][7], (hB).y, b7, acc2[3][7]);                      \
    } while (0)

// 32x256 <- 32x256 @ 256x256 ; 128 threads, per-thread tile 8 rows x 8 cols.
// Weights staged through an 8-row SMEM buffer (ws): one cooperative LDG fill per
// block per 8-k group (software-pipelined into registers during the previous
// group's FMAs), consumed via conflict-free LDS.128 (4 wf vs 8 wf for LDG).
template <int MODE>
__device__ __forceinline__ void gemm256(const float* __restrict__ Wg,
                                        const float* __restrict__ bias,
                                        const float* __restrict__ w3,
                                        const float* __restrict__ hin,
                                        float* hout, float* ws, int tid) {
    const int tx = tid & 31, ty = tid >> 5;   // ty: 0..3
    const int j0 = tx * 8, m0 = ty * 8;

    ULL acc2[4][8];                           // [row-pair][col]
#pragma unroll
    for (int p = 0; p < 4; p++)
#pragma unroll
        for (int c = 0; c < 8; c++) acc2[p][c] = 0ULL;

    // fill indices for the 8x256 weight group (2048 floats = 512 float4)
    float4 wreg[4];
#pragma unroll
    for (int i = 0; i < 4; i++) {
        int idx = tid + i * NTHREADS;         // 0..511
        int krow = idx >> 6, col4 = (idx & 63) << 2;
        wreg[i] = *(const float4*)(Wg + (size_t)krow * 256 + col4);
    }

#pragma unroll 1
    for (int kg = 0; kg < 256; kg += 8) {
        __syncthreads();                      // previous group fully consumed
#pragma unroll
        for (int i = 0; i < 4; i++) {
            int idx = tid + i * NTHREADS;
            int krow = idx >> 6, col4 = (idx & 63) << 2;
            *(float4*)(ws + krow * 256 + col4) = wreg[i];
        }
        __syncthreads();                      // group ready

        if (kg + 8 < 256) {                   // prefetch next group during FMAs
#pragma unroll
            for (int i = 0; i < 4; i++) {
                int idx = tid + i * NTHREADS;
                int krow = idx >> 6, col4 = (idx & 63) << 2;
                wreg[i] = *(const float4*)(Wg + (size_t)(kg + 8 + krow) * 256 + col4);
            }
        }

#pragma unroll
        for (int c = 0; c < 2; c++) {         // 2 chunks of 4 k
            const int k4 = kg + 4 * c;
            const int pma = m0 ^ swz_f(k4);
            const int pmb = pma ^ 4;
#pragma unroll
            for (int kk = 0; kk < 4; kk++) {
                const float* hr = hin + (k4 + kk) * 32;
                ulonglong2 hA = *(const ulonglong2*)(hr + pma);   // rows m0..m0+3
                ulonglong2 hB = *(const ulonglong2*)(hr + pmb);   // rows m0+4..m0+7
                const float* wr = ws + (4 * c + kk) * 256 + j0;
                float4 wva = *(const float4*)(wr);
                float4 wvb = *(const float4*)(wr + 4);
                KSTEP8(hA, hB, wva, wvb);
            }
        }
    }

    // unpack accumulators: vals[c][r] for rows m0+r
    float vals[8][8];
#pragma unroll
    for (int p = 0; p < 4; p++)
#pragma unroll
        for (int c = 0; c < 8; c++) {
            unsigned int lo, hi;
            UNPACK2(lo, hi, acc2[p][c]);
            vals[c][2 * p + 0] = __uint_as_float(lo);
            vals[c][2 * p + 1] = __uint_as_float(hi);
        }

    // writer offset: rows j0..j0+7 all have (row>>3)==tx -> f = 4*(tx&7)
    const int pj  = m0 ^ (4 * (tx & 7));
    const int pjb = pj ^ 4;

    if (MODE == M_TANH || MODE == M_D3) {
        float bj[8];
        {
            float4 a = *(const float4*)(bias + j0);
            float4 b = *(const float4*)(bias + j0 + 4);
            bj[0] = a.x; bj[1] = a.y; bj[2] = a.z; bj[3] = a.w;
            bj[4] = b.x; bj[5] = b.y; bj[6] = b.z; bj[7] = b.w;
        }
        float w3c[8];
        if (MODE == M_D3) {
            float4 a = *(const float4*)(w3 + j0);
            float4 b = *(const float4*)(w3 + j0 + 4);
            w3c[0] = a.x; w3c[1] = a.y; w3c[2] = a.z; w3c[3] = a.w;
            w3c[4] = b.x; w3c[5] = b.y; w3c[6] = b.z; w3c[7] = b.w;
        }
#pragma unroll
        for (int c = 0; c < 8; c++) {
            float z[8];
#pragma unroll
            for (int r = 0; r < 8; r++) {
                float h = tanh_fast(vals[c][r] + bj[c]);
                z[r] = (MODE == M_TANH) ? h : (w3c[c] * (1.0f - h * h));
            }
            float* rowp = hout + (j0 + c) * 32;
            *(float4*)(rowp + pj)  = make_float4(z[0], z[1], z[2], z[3]);
            *(float4*)(rowp + pjb) = make_float4(z[4], z[5], z[6], z[7]);
        }
    } else {  // M_BWD: in-place dz = acc * (1 - h^2)
#pragma unroll
        for (int c = 0; c < 8; c++) {
            float* rowp = hout + (j0 + c) * 32;
            float4 ha = *(const float4*)(rowp + pj);
            float4 hb = *(const float4*)(rowp + pjb);
            float4 va, vb;
            va.x = vals[c][0] * (1.0f - ha.x * ha.x);
            va.y = vals[c][1] * (1.0f - ha.y * ha.y);
            va.z = vals[c][2] * (1.0f - ha.z * ha.z);
            va.w = vals[c][3] * (1.0f - ha.w * ha.w);
            vb.x = vals[c][4] * (1.0f - hb.x * hb.x);
            vb.y = vals[c][5] * (1.0f - hb.y * hb.y);
            vb.z = vals[c][6] * (1.0f - hb.z * hb.z);
            vb.w = vals[c][7] * (1.0f - hb.w * hb.w);
            *(float4*)(rowp + pj)  = va;
            *(float4*)(rowp + pjb) = vb;
        }
    }
}

__global__ void __launch_bounds__(NTHREADS, 2) ode_kernel(
    const float* __restrict__ v,  const float* __restrict__ w,
    const float* __restrict__ x,  const float* __restrict__ q,
    const float* __restrict__ W0, const float* __restrict__ b0,
    const float* __restrict__ W1, const float* __restrict__ b1,
    const float* __restrict__ W2, const float* __restrict__ b2,
    const float* __restrict__ W3,
    float* __restrict__ out) {
    extern __shared__ float smem[];
    float* h1s = smem;                    // hT layout [256][32]
    float* h2s = h1s + 256 * 32;
    float* d3s = h2s + 256 * 32;
    float* rqs = d3s + 256 * 32;          // [32][12] : r(3), qn0(4), qn1(4)
    float* grs = rqs + TILE * 12;         // [32][12] : grad_rq
    float* ws  = grs + TILE * 12;         // [8][256] weight stage (8 KB)

    const int tid = threadIdx.x;
    const size_t row0 = (size_t)blockIdx.x * TILE;

    // ---- dxdt = v (pure copy, coalesced) ----
    {
        const size_t base = row0 * 6;
#pragma unroll
        for (int i = 0; i < 2; i++) {
            int idx = tid + i * NTHREADS;
            if (idx < TILE * 6)
                out[(size_t)12 * Bc + base + idx] = v[base + idx];
        }
    }

    // ---- build rq = [r, qn0, qn1] ----
    if (tid < TILE) {
        int m = tid;
        size_t g = row0 + m;
        float4 qa = *(const float4*)(q + g * 8);
        float4 qb = *(const float4*)(q + g * 8 + 4);
        float n0 = rsqrtf(qa.x * qa.x + qa.y * qa.y + qa.z * qa.z + qa.w * qa.w);
        float n1 = rsqrtf(qb.x * qb.x + qb.y * qb.y + qb.z * qb.z + qb.w * qb.w);
        const float* xp = x + g * 6;
        float* rp = rqs + m * 12;
        rp[0] = xp[3] - xp[0];
        rp[1] = xp[4] - xp[1];
        rp[2] = xp[5] - xp[2];
        rp[3] = qa.x * n0; rp[4] = qa.y * n0; rp[5] = qa.z * n0; rp[6] = qa.w * n0;
        rp[7] = qb.x * n1; rp[8] = qb.y * n1; rp[9] = qb.z * n1; rp[10] = qb.w * n1;
        rp[11] = 0.0f;
    }
    __syncthreads();

    // ---- layer 0: h1T[j][m] = tanh(rq[m].W0[:,j] + b0[j]); 2 neurons per thread ----
    {
#pragma unroll
        for (int jj = 0; jj < 2; jj++) {
            int j = tid + jj * NTHREADS;
            float wcol[11];
#pragma unroll
            for (int k = 0; k < 11; k++) wcol[k] = W0[k * 256 + j];
            float bb = b0[j];
            float z[32];
#pragma unroll 4
            for (int m = 0; m < TILE; m++) {
                const float* rp = rqs + m * 12;
                float zz = bb;
#pragma unroll
                for (int k = 0; k < 11; k++) zz = fmaf(rp[k], wcol[k], zz);
                z[m] = tanh_fast(zz);
            }
            const int f = swz_f(j);
            float* rowp = h1s + j * 32;
#pragma unroll
            for (int mr = 0; mr < 32; mr += 4) {
                int pr = mr ^ f;
                *(float4*)(rowp + pr) = make_float4(z[mr], z[mr + 1], z[mr + 2], z[mr + 3]);
            }
        }
    }
    __syncthreads();

    gemm256<M_TANH>(W1, b1, nullptr, h1s, h2s, ws, tid);         // h2 = tanh(h1 W1 + b1)
    __syncthreads();
    gemm256<M_D3>(W2, b2, W3, h2s, d3s, ws, tid);                // dz3 = W3*(1-h3^2)
    __syncthreads();
    gemm256<M_BWD>(g_W2T, nullptr, nullptr, d3s, h2s, ws, tid);  // dz2 (in-place over h2)
    __syncthreads();
    gemm256<M_BWD>(g_W1T, nullptr, nullptr, h2s, h1s, ws, tid);  // dz1 (in-place over h1)
    __syncthreads();

    // ---- grad_rq[k] = sum_j W0[k][j] * dz1[j] ; 4 threads per row ----
    {
        int m = tid >> 2, kq = tid & 3;
        float a[11];
#pragma unroll
        for (int k = 0; k < 11; k++) a[k] = 0.0f;
        int jb = kq * 64;
#pragma unroll 4
        for (int j = jb; j < jb + 64; j++) {
            float d = h1s[j * 32 + (m ^ swz_f(j))];
            float4 wA = *(const float4*)(g_W0T + j * 12);
            float4 wB = *(const float4*)(g_W0T + j * 12 + 4);
            float4 wC = *(const float4*)(g_W0T + j * 12 + 8);
            a[0] = fmaf(d, wA.x, a[0]); a[1] = fmaf(d, wA.y, a[1]);
            a[2] = fmaf(d, wA.z, a[2]); a[3] = fmaf(d, wA.w, a[3]);
            a[4] = fmaf(d, wB.x, a[4]); a[5] = fmaf(d, wB.y, a[5]);
            a[6] = fmaf(d, wB.z, a[6]); a[7] = fmaf(d, wB.w, a[7]);
            a[8] = fmaf(d, wC.x, a[8]); a[9] = fmaf(d, wC.y, a[9]);
            a[10] = fmaf(d, wC.z, a[10]);
        }
#pragma unroll
        for (int k = 0; k < 11; k++) {
            a[k] += __shfl_xor_sync(0xffffffffu, a[k], 1);
            a[k] += __shfl_xor_sync(0xffffffffu, a[k], 2);
        }
        if (kq == 0) {
#pragma unroll
            for (int k = 0; k < 11; k++) grs[m * 12 + k] = a[k];
        }
    }
    __syncthreads();

    // ---- epilogue: quaternion dynamics + outputs (one thread per (row, particle)) ----
    if (tid < TILE * 2) {
        int m = tid >> 1, p = tid & 1;
        size_t g = row0 + m;
        size_t e = g * 2 + p;
        const float* rp = rqs + m * 12;
        const float* gp = grs + m * 12;
        float q0 = rp[3 + 4 * p], q1 = rp[4 + 4 * p], q2 = rp[5 + 4 * p], q3 = rp[6 + 4 * p];
        float gq0 = gp[3 + 4 * p], gq1 = gp[4 + 4 * p], gq2 = gp[5 + 4 * p], gq3 = gp[6 + 4 * p];
        float wx = w[e * 3 + 0], wy = w[e * 3 + 1], wz = w[e * 3 + 2];

        // dqdt = 0.5 * qn * (0, w)   (real-first Hamilton product)
        float dq0 = -0.5f * (q1 * wx + q2 * wy + q3 * wz);
        float dq1 =  0.5f * (q0 * wx + q2 * wz - q3 * wy);
        float dq2 =  0.5f * (q0 * wy - q1 * wz + q3 * wx);
        float dq3 =  0.5f * (q0 * wz + q1 * wy - q2 * wx);
        out[(size_t)18 * Bc + e * 4 + 0] = dq0;
        out[(size_t)18 * Bc + e * 4 + 1] = dq1;
        out[(size_t)18 * Bc + e * 4 + 2] = dq2;
        out[(size_t)18 * Bc + e * 4 + 3] = dq3;

        float Gq[3][4] = {{-q1,  q0,  q3, -q2},
                          {-q2, -q3,  q0,  q1},
                          {-q3,  q2, -q1,  q0}};
        float Gd[3][4] = {{-dq1,  dq0,  dq3, -dq2},
                          {-dq2, -dq3,  dq0,  dq1},
                          {-dq3,  dq2, -dq1,  dq0}};
        float l0 = wx * 1.0f, l1 = wy * 2.0f, l2 = wz * 3.0f;
        float gqv[4] = {gq0, gq1, gq2, gq3};
#pragma unroll
        for (int i = 0; i < 3; i++) {
            float O0 = 2.0f * (Gq[i][0] * Gd[0][0] + Gq[i][1] * Gd[0][1] + Gq[i][2] * Gd[0][2] + Gq[i][3] * Gd[0][3]);
            float O1 = 2.0f * (Gq[i][0] * Gd[1][0] + Gq[i][1] * Gd[1][1] + Gq[i][2] * Gd[1][2] + Gq[i][3] * Gd[1][3]);
            float O2 = 2.0f * (Gq[i][0] * Gd[2][0] + Gq[i][1] * Gd[2][1] + Gq[i][2] * Gd[2][2] + Gq[i][3] * Gd[2][3]);
            float t = -(O0 * l0 + O1 * l1 + O2 * l2)
                      - 0.5f * (Gq[i][0] * gqv[0] + Gq[i][1] * gqv[1] + Gq[i][2] * gqv[2] + Gq[i][3] * gqv[3]);
            out[(size_t)6 * Bc + e * 3 + i] = t / (float)(i + 1);
        }

        // dvdt = +-(grad_r + harm)/MASS
        float r0 = rp[0], r1 = rp[1], r2 = rp[2];
        float rn = sqrtf(r0 * r0 + r1 * r1 + r2 * r2);
        float coef = 100.0f * (rn - 1.0f) / rn;
        float sgn = p ? -1.0f : 1.0f;
        out[e * 3 + 0] = sgn * (gp[0] + coef * r0) / 7.0f;
        out[e * 3 + 1] = sgn * (gp[1] + coef * r1) / 7.0f;
        out[e * 3 + 2] = sgn * (gp[2] + coef * r2) / 7.0f;
    }
}

extern "C" void kernel_launch(void* const* d_in, const int* in_sizes, int n_in,
                              void* d_out, int out_size) {
    const float* v  = (const float*)d_in[0];
    const float* w  = (const float*)d_in[1];
    const float* x  = (const float*)d_in[2];
    const float* q  = (const float*)d_in[3];
    const float* W0 = (const float*)d_in[4];
    const float* b0 = (const float*)d_in[5];
    const float* W1 = (const float*)d_in[6];
    const float* b1 = (const float*)d_in[7];
    const float* W2 = (const float*)d_in[8];
    const float* b2 = (const float*)d_in[9];
    const float* W3 = (const float*)d_in[10];
    float* out = (float*)d_out;

    constexpr size_t SMEM_BYTES =
        (size_t)(3 * 256 * 32 + 2 * TILE * 12 + 8 * 256) * sizeof(float);
    cudaFuncSetAttribute(ode_kernel, cudaFuncAttributeMaxDynamicSharedMemorySize,
                         (int)SMEM_BYTES);

    transpose_kernel<<<256, 256>>>(W0, W1, W2);
    ode_kernel<<<Bc / TILE, NTHREADS, SMEM_BYTES>>>(v, w, x, q, W0, b0, W1, b1,
                                                    W2, b2, W3, out);
}

// round 16
// speedup vs baseline: 1.1593x; 1.1593x over previous
#include <cuda_runtime.h>
#include <cstdint>

#define Bc      131072
#define TILE    32
#define NTHREADS 128
// transposed activation layout: hT[k][m], k=0..255, m=0..31 (32 floats/row, swizzled)

typedef unsigned long long ULL;

// ---------------- device scratch (no allocations allowed) ----------------
__device__ float g_W1T[256 * 256];
__device__ float g_W2T[256 * 256];
__device__ float g_W0T[256 * 12];   // [j][k], k padded 11->12

__global__ void transpose_kernel(const float* __restrict__ W0,
                                 const float* __restrict__ W1,
                                 const float* __restrict__ W2) {
    int i = blockIdx.x;      // 0..255 (source row)
    int j = threadIdx.x;     // 0..255 (source col)
    g_W1T[j * 256 + i] = W1[i * 256 + j];
    g_W2T[j * 256 + i] = W2[i * 256 + j];
    if (i < 11)  g_W0T[j * 12 + i] = W0[i * 256 + j];
    if (i == 11) g_W0T[j * 12 + 11] = 0.0f;
}

// accurate-enough tanh: 2 MUFU (EX2 + RCP), abs err ~1e-7
__device__ __forceinline__ float tanh_fast(float x) {
    float xc = fminf(fmaxf(x, -15.0f), 15.0f);
    float e  = __expf(2.0f * xc);
    return __fdividef(e - 1.0f, e + 1.0f);
}

// packed f32x2 helpers
#define FMA2(d, a, b, c) \
    asm("fma.rn.f32x2 %0, %1, %2, %3;" : "=l"(d) : "l"(a), "l"(b), "l"(c))
#define BCAST2(d, s) \
    asm("mov.b64 %0, {%1, %1};" : "=l"(d) : "r"(s))
#define UNPACK2(lo, hi, s) \
    asm("mov.b64 {%0, %1}, %2;" : "=r"(lo), "=r"(hi) : "l"(s))

// swizzle: element (row, m) lives at  row*32 + (m ^ (4*((row>>3)&7)))
__device__ __forceinline__ int swz_f(int row) { return 4 * ((row >> 3) & 7); }

#define M_TANH 0   // hout = tanh(acc + bias)
#define M_D3   1   // h3 = tanh(acc + bias); hout = W3[j] * (1 - h3^2)
#define M_BWD  2   // hout = acc * (1 - hout^2)   (in-place, hout holds forward act)

// 32 FFMA2 for one k-step: row pairs in hA (m0..m0+3) / hB (m0+4..m0+7),
// 8 weight cols in wva (j0..j0+3) / wvb (j0+4..j0+7)
#define KSTEP8(hA, hB, wva, wvb)                                       \
    do {                                                               \
        ULL b0, b1, b2, b3, b4, b5, b6, b7;                            \
        BCAST2(b0, __float_as_uint((wva).x));                          \
        BCAST2(b1, __float_as_uint((wva).y));                          \
        BCAST2(b2, __float_as_uint((wva).z));                          \
        BCAST2(b3, __float_as_uint((wva).w));                          \
        BCAST2(b4, __float_as_uint((wvb).x));                          \
        BCAST2(b5, __float_as_uint((wvb).y));                          \
        BCAST2(b6, __float_as_uint((wvb).z));                          \
        BCAST2(b7, __float_as_uint((wvb).w));                          \
        FMA2(acc2[0][0], (hA).x, b0, acc2[0][0]);                      \
        FMA2(acc2[1][0], (hA).y, b0, acc2[1][0]);                      \
        FMA2(acc2[2][0], (hB).x, b0, acc2[2][0]);                      \
        FMA2(acc2[3][0], (hB).y, b0, acc2[3][0]);                      \
        FMA2(acc2[0][1], (hA).x, b1, acc2[0][1]);                      \
        FMA2(acc2[1][1], (hA).y, b1, acc2[1][1]);                      \
        FMA2(acc2[2][1], (hB).x, b1, acc2[2][1]);                      \
        FMA2(acc2[3][1], (hB).y, b1, acc2[3][1]);                      \
        FMA2(acc2[0][2], (hA).x, b2, acc2[0][2]);                      \
        FMA2(acc2[1][2], (hA).y, b2, acc2[1][2]);                      \
        FMA2(acc2[2][2], (hB).x, b2, acc2[2][2]);                      \
        FMA2(acc2[3][2], (hB).y, b2, acc2[3][2]);                      \
        FMA2(acc2[0][3], (hA).x, b3, acc2[0][3]);                      \
        FMA2(acc2[1][3], (hA).y, b3, acc2[1][3]);                      \
        FMA2(acc2[2][3], (hB).x, b3, acc2[2][3]);                      \
        FMA2(acc2[3][3], (hB).y, b3, acc2[3][3]);                      \
        FMA2(acc2[0][4], (hA).x, b4, acc2[0][4]);                      \
        FMA2(acc2[1][4], (hA).y, b4, acc2[1][4]);                      \
        FMA2(acc2[2][4], (hB).x, b4, acc2[2][4]);                      \
        FMA2(acc2[3][4], (hB).y, b4, acc2[3][4]);                      \
        FMA2(acc2[0][5], (hA).x, b5, acc2[0][5]);                      \
        FMA2(acc2[1][5], (hA).y, b5, acc2[1][5]);                      \
        FMA2(acc2[2][5], (hB).x, b5, acc2[2][5]);                      \
        FMA2(acc2[3][5], (hB).y, b5, acc2[3][5]);                      \
        FMA2(acc2[0][6], (hA).x, b6, acc2[0][6]);                      \
        FMA2(acc2[1][6], (hA).y, b6, acc2[1][6]);                      \
        FMA2(acc2[2][6], (hB).x, b6, acc2[2][6]);                      \
        FMA2(acc2[3][6], (hB).y, b6, acc2[3][6]);                      \
        FMA2(acc2[0][7], (hA).x, b7, acc2[0][7]);                      \
        FMA2(acc2[1][7], (hA).y, b7, acc2[1][7]);                      \
        FMA2(acc2[2][7], (hB).x, b7, acc2[2][7]);                      \
        FMA2(acc2[3][7], (hB).y, b7, acc2[3][7]);                      \
    } while (0)

// 32x256 <- 32x256 @ 256x256 ; 128 threads, per-thread tile 8 rows x 8 cols.
// Lane map: c = lane&7 (col-group), rg = lane>>3 (row-group); warp ty owns a
// 64-col j-slice. 4 lanes share each weight address -> LDG dedups to 2 wf per
// instruction (was 4), halving weight L1 traffic vs the col-spanning map.
template <int MODE>
__device__ __forceinline__ void gemm256(const float* __restrict__ Wg,
                                        const float* __restrict__ bias,
                                        const float* __restrict__ w3,
                                        const float* __restrict__ hin,
                                        float* hout, int tid) {
    const int lane = tid & 31, ty = tid >> 5; // ty: 0..3 (warp j-slice)
    const int c = lane & 7, rg = lane >> 3;   // col-group, row-group
    const int j0 = ty * 64 + c * 8, m0 = rg * 8;

    ULL acc2[4][8];                           // [row-pair][col]
#pragma unroll
    for (int p = 0; p < 4; p++)
#pragma unroll
        for (int cc = 0; cc < 8; cc++) acc2[p][cc] = 0ULL;

    float4 wcA[4], wcB[4];
#pragma unroll
    for (int kk = 0; kk < 4; kk++) {
        wcA[kk] = *(const float4*)(Wg + (size_t)kk * 256 + j0);
        wcB[kk] = *(const float4*)(Wg + (size_t)kk * 256 + j0 + 4);
    }

#pragma unroll 1
    for (int k4 = 0; k4 < 256; k4 += 4) {
        const int fk  = swz_f(k4);            // constant within the 4-chunk
        const int pma = m0 ^ fk;
        const int pmb = pma ^ 4;

        const int k4n = (k4 + 4) & 255;       // in-bounds wrap
        float4 wnA[4], wnB[4];
#pragma unroll
        for (int kk = 0; kk < 4; kk++) {
            wnA[kk] = *(const float4*)(Wg + (size_t)(k4n + kk) * 256 + j0);
            wnB[kk] = *(const float4*)(Wg + (size_t)(k4n + kk) * 256 + j0 + 4);
        }

#pragma unroll
        for (int kk = 0; kk < 4; kk++) {
            const float* hr = hin + (k4 + kk) * 32;
            ulonglong2 hA = *(const ulonglong2*)(hr + pma);   // rows m0..m0+3
            ulonglong2 hB = *(const ulonglong2*)(hr + pmb);   // rows m0+4..m0+7
            KSTEP8(hA, hB, wcA[kk], wcB[kk]);
        }
#pragma unroll
        for (int kk = 0; kk < 4; kk++) { wcA[kk] = wnA[kk]; wcB[kk] = wnB[kk]; }
    }

    // unpack accumulators: vals[cc][r] for rows m0+r
    float vals[8][8];
#pragma unroll
    for (int p = 0; p < 4; p++)
#pragma unroll
        for (int cc = 0; cc < 8; cc++) {
            unsigned int lo, hi;
            UNPACK2(lo, hi, acc2[p][cc]);
            vals[cc][2 * p + 0] = __uint_as_float(lo);
            vals[cc][2 * p + 1] = __uint_as_float(hi);
        }

    // writer offset: rows j0..j0+7 share (row>>3) = ty*8 + c
    const int pj  = m0 ^ (4 * ((ty * 8 + c) & 7));
    const int pjb = pj ^ 4;

    if (MODE == M_TANH || MODE == M_D3) {
        float bj[8];
        {
            float4 a = *(const float4*)(bias + j0);
            float4 b = *(const float4*)(bias + j0 + 4);
            bj[0] = a.x; bj[1] = a.y; bj[2] = a.z; bj[3] = a.w;
            bj[4] = b.x; bj[5] = b.y; bj[6] = b.z; bj[7] = b.w;
        }
        float w3c[8];
        if (MODE == M_D3) {
            float4 a = *(const float4*)(w3 + j0);
            float4 b = *(const float4*)(w3 + j0 + 4);
            w3c[0] = a.x; w3c[1] = a.y; w3c[2] = a.z; w3c[3] = a.w;
            w3c[4] = b.x; w3c[5] = b.y; w3c[6] = b.z; w3c[7] = b.w;
        }
#pragma unroll
        for (int cc = 0; cc < 8; cc++) {
            float z[8];
#pragma unroll
            for (int r = 0; r < 8; r++) {
                float h = tanh_fast(vals[cc][r] + bj[cc]);
                z[r] = (MODE == M_TANH) ? h : (w3c[cc] * (1.0f - h * h));
            }
            float* rowp = hout + (j0 + cc) * 32;
            *(float4*)(rowp + pj)  = make_float4(z[0], z[1], z[2], z[3]);
            *(float4*)(rowp + pjb) = make_float4(z[4], z[5], z[6], z[7]);
        }
    } else {  // M_BWD: in-place dz = acc * (1 - h^2)
#pragma unroll
        for (int cc = 0; cc < 8; cc++) {
            float* rowp = hout + (j0 + cc) * 32;
            float4 ha = *(const float4*)(rowp + pj);
            float4 hb = *(const float4*)(rowp + pjb);
            float4 va, vb;
            va.x = vals[cc][0] * (1.0f - ha.x * ha.x);
            va.y = vals[cc][1] * (1.0f - ha.y * ha.y);
            va.z = vals[cc][2] * (1.0f - ha.z * ha.z);
            va.w = vals[cc][3] * (1.0f - ha.w * ha.w);
            vb.x = vals[cc][4] * (1.0f - hb.x * hb.x);
            vb.y = vals[cc][5] * (1.0f - hb.y * hb.y);
            vb.z = vals[cc][6] * (1.0f - hb.z * hb.z);
            vb.w = vals[cc][7] * (1.0f - hb.w * hb.w);
            *(float4*)(rowp + pj)  = va;
            *(float4*)(rowp + pjb) = vb;
        }
    }
}

__global__ void __launch_bounds__(NTHREADS, 2) ode_kernel(
    const float* __restrict__ v,  const float* __restrict__ w,
    const float* __restrict__ x,  const float* __restrict__ q,
    const float* __restrict__ W0, const float* __restrict__ b0,
    const float* __restrict__ W1, const float* __restrict__ b1,
    const float* __restrict__ W2, const float* __restrict__ b2,
    const float* __restrict__ W3,
    float* __restrict__ out) {
    extern __shared__ float smem[];
    float* h1s = smem;                    // hT layout [256][32]
    float* h2s = h1s + 256 * 32;
    float* d3s = h2s + 256 * 32;
    float* rqs = d3s + 256 * 32;          // [32][12] : r(3), qn0(4), qn1(4)
    float* grs = rqs + TILE * 12;         // [32][12] : grad_rq

    const int tid = threadIdx.x;
    const size_t row0 = (size_t)blockIdx.x * TILE;

    // ---- dxdt = v (pure copy, coalesced) ----
    {
        const size_t base = row0 * 6;
#pragma unroll
        for (int i = 0; i < 2; i++) {
            int idx = tid + i * NTHREADS;
            if (idx < TILE * 6)
                out[(size_t)12 * Bc + base + idx] = v[base + idx];
        }
    }

    // ---- build rq = [r, qn0, qn1] ----
    if (tid < TILE) {
        int m = tid;
        size_t g = row0 + m;
        float4 qa = *(const float4*)(q + g * 8);
        float4 qb = *(const float4*)(q + g * 8 + 4);
        float n0 = rsqrtf(qa.x * qa.x + qa.y * qa.y + qa.z * qa.z + qa.w * qa.w);
        float n1 = rsqrtf(qb.x * qb.x + qb.y * qb.y + qb.z * qb.z + qb.w * qb.w);
        const float* xp = x + g * 6;
        float* rp = rqs + m * 12;
        rp[0] = xp[3] - xp[0];
        rp[1] = xp[4] - xp[1];
        rp[2] = xp[5] - xp[2];
        rp[3] = qa.x * n0; rp[4] = qa.y * n0; rp[5] = qa.z * n0; rp[6] = qa.w * n0;
        rp[7] = qb.x * n1; rp[8] = qb.y * n1; rp[9] = qb.z * n1; rp[10] = qb.w * n1;
        rp[11] = 0.0f;
    }
    __syncthreads();

    // ---- layer 0: h1T[j][m] = tanh(rq[m].W0[:,j] + b0[j]); 2 neurons per thread ----
    {
#pragma unroll
        for (int jj = 0; jj < 2; jj++) {
            int j = tid + jj * NTHREADS;
            float wcol[11];
#pragma unroll
            for (int k = 0; k < 11; k++) wcol[k] = W0[k * 256 + j];
            float bb = b0[j];
            float z[32];
#pragma unroll 4
            for (int m = 0; m < TILE; m++) {
                const float* rp = rqs + m * 12;
                float zz = bb;
#pragma unroll
                for (int k = 0; k < 11; k++) zz = fmaf(rp[k], wcol[k], zz);
                z[m] = tanh_fast(zz);
            }
            const int f = swz_f(j);
            float* rowp = h1s + j * 32;
#pragma unroll
            for (int mr = 0; mr < 32; mr += 4) {
                int pr = mr ^ f;
                *(float4*)(rowp + pr) = make_float4(z[mr], z[mr + 1], z[mr + 2], z[mr + 3]);
            }
        }
    }
    __syncthreads();

    gemm256<M_TANH>(W1, b1, nullptr, h1s, h2s, tid);         // h2 = tanh(h1 W1 + b1)
    __syncthreads();
    gemm256<M_D3>(W2, b2, W3, h2s, d3s, tid);                // dz3 = W3*(1-h3^2)
    __syncthreads();
    gemm256<M_BWD>(g_W2T, nullptr, nullptr, d3s, h2s, tid);  // dz2 (in-place over h2)
    __syncthreads();
    gemm256<M_BWD>(g_W1T, nullptr, nullptr, h2s, h1s, tid);  // dz1 (in-place over h1)
    __syncthreads();

    // ---- grad_rq[k] = sum_j W0[k][j] * dz1[j] ; 4 threads per row ----
    {
        int m = tid >> 2, kq = tid & 3;
        float a[11];
#pragma unroll
        for (int k = 0; k < 11; k++) a[k] = 0.0f;
        int jb = kq * 64;
#pragma unroll 4
        for (int j = jb; j < jb + 64; j++) {
            float d = h1s[j * 32 + (m ^ swz_f(j))];
            float4 wA = *(const float4*)(g_W0T + j * 12);
            float4 wB = *(const float4*)(g_W0T + j * 12 + 4);
            float4 wC = *(const float4*)(g_W0T + j * 12 + 8);
            a[0] = fmaf(d, wA.x, a[0]); a[1] = fmaf(d, wA.y, a[1]);
            a[2] = fmaf(d, wA.z, a[2]); a[3] = fmaf(d, wA.w, a[3]);
            a[4] = fmaf(d, wB.x, a[4]); a[5] = fmaf(d, wB.y, a[5]);
            a[6] = fmaf(d, wB.z, a[6]); a[7] = fmaf(d, wB.w, a[7]);
            a[8] = fmaf(d, wC.x, a[8]); a[9] = fmaf(d, wC.y, a[9]);
            a[10] = fmaf(d, wC.z, a[10]);
        }
#pragma unroll
        for (int k = 0; k < 11; k++) {
            a[k] += __shfl_xor_sync(0xffffffffu, a[k], 1);
            a[k] += __shfl_xor_sync(0xffffffffu, a[k], 2);
        }
        if (kq == 0) {
#pragma unroll
            for (int k = 0; k < 11; k++) grs[m * 12 + k] = a[k];
        }
    }
    __syncthreads();

    // ---- epilogue: quaternion dynamics + outputs (one thread per (row, particle)) ----
    if (tid < TILE * 2) {
        int m = tid >> 1, p = tid & 1;
        size_t g = row0 + m;
        size_t e = g * 2 + p;
        const float* rp = rqs + m * 12;
        const float* gp = grs + m * 12;
        float q0 = rp[3 + 4 * p], q1 = rp[4 + 4 * p], q2 = rp[5 + 4 * p], q3 = rp[6 + 4 * p];
        float gq0 = gp[3 + 4 * p], gq1 = gp[4 + 4 * p], gq2 = gp[5 + 4 * p], gq3 = gp[6 + 4 * p];
        float wx = w[e * 3 + 0], wy = w[e * 3 + 1], wz = w[e * 3 + 2];

        // dqdt = 0.5 * qn * (0, w)   (real-first Hamilton product)
        float dq0 = -0.5f * (q1 * wx + q2 * wy + q3 * wz);
        float dq1 =  0.5f * (q0 * wx + q2 * wz - q3 * wy);
        float dq2 =  0.5f * (q0 * wy - q1 * wz + q3 * wx);
        float dq3 =  0.5f * (q0 * wz + q1 * wy - q2 * wx);
        out[(size_t)18 * Bc + e * 4 + 0] = dq0;
        out[(size_t)18 * Bc + e * 4 + 1] = dq1;
        out[(size_t)18 * Bc + e * 4 + 2] = dq2;
        out[(size_t)18 * Bc + e * 4 + 3] = dq3;

        float Gq[3][4] = {{-q1,  q0,  q3, -q2},
                          {-q2, -q3,  q0,  q1},
                          {-q3,  q2, -q1,  q0}};
        float Gd[3][4] = {{-dq1,  dq0,  dq3, -dq2},
                          {-dq2, -dq3,  dq0,  dq1},
                          {-dq3,  dq2, -dq1,  dq0}};
        float l0 = wx * 1.0f, l1 = wy * 2.0f, l2 = wz * 3.0f;
        float gqv[4] = {gq0, gq1, gq2, gq3};
#pragma unroll
        for (int i = 0; i < 3; i++) {
            float O0 = 2.0f * (Gq[i][0] * Gd[0][0] + Gq[i][1] * Gd[0][1] + Gq[i][2] * Gd[0][2] + Gq[i][3] * Gd[0][3]);
            float O1 = 2.0f * (Gq[i][0] * Gd[1][0] + Gq[i][1] * Gd[1][1] + Gq[i][2] * Gd[1][2] + Gq[i][3] * Gd[1][3]);
            float O2 = 2.0f * (Gq[i][0] * Gd[2][0] + Gq[i][1] * Gd[2][1] + Gq[i][2] * Gd[2][2] + Gq[i][3] * Gd[2][3]);
            float t = -(O0 * l0 + O1 * l1 + O2 * l2)
                      - 0.5f * (Gq[i][0] * gqv[0] + Gq[i][1] * gqv[1] + Gq[i][2] * gqv[2] + Gq[i][3] * gqv[3]);
            out[(size_t)6 * Bc + e * 3 + i] = t / (float)(i + 1);
        }

        // dvdt = +-(grad_r + harm)/MASS
        float r0 = rp[0], r1 = rp[1], r2 = rp[2];
        float rn = sqrtf(r0 * r0 + r1 * r1 + r2 * r2);
        float coef = 100.0f * (rn - 1.0f) / rn;
        float sgn = p ? -1.0f : 1.0f;
        out[e * 3 + 0] = sgn * (gp[0] + coef * r0) / 7.0f;
        out[e * 3 + 1] = sgn * (gp[1] + coef * r1) / 7.0f;
        out[e * 3 + 2] = sgn * (gp[2] + coef * r2) / 7.0f;
    }
}

extern "C" void kernel_launch(void* const* d_in, const int* in_sizes, int n_in,
                              void* d_out, int out_size) {
    const float* v  = (const float*)d_in[0];
    const float* w  = (const float*)d_in[1];
    const float* x  = (const float*)d_in[2];
    const float* q  = (const float*)d_in[3];
    const float* W0 = (const float*)d_in[4];
    const float* b0 = (const float*)d_in[5];
    const float* W1 = (const float*)d_in[6];
    const float* b1 = (const float*)d_in[7];
    const float* W2 = (const float*)d_in[8];
    const float* b2 = (const float*)d_in[9];
    const float* W3 = (const float*)d_in[10];
    float* out = (float*)d_out;

    constexpr size_t SMEM_BYTES = (size_t)(3 * 256 * 32 + 2 * TILE * 12) * sizeof(float);
    cudaFuncSetAttribute(ode_kernel, cudaFuncAttributeMaxDynamicSharedMemorySize,
                         (int)SMEM_BYTES);

    transpose_kernel<<<256, 256>>>(W0, W1, W2);
    ode_kernel<<<Bc / TILE, NTHREADS, SMEM_BYTES>>>(v, w, x, q, W0, b0, W1, b1,
                                                    W2, b2, W3, out);
}

// round 17
// speedup vs baseline: 2.0148x; 1.7380x over previous
#include <cuda_runtime.h>
#include <cuda_bf16.h>
#include <cstdint>

#define Bc      131072
#define TILE    32
#define NTHREADS 256
#define PROW    264                    // bf16 plane row stride (elements), pad for ldmatrix banks
#define PLANE   (32 * PROW)            // elements per plane
#define PLANE_B (PLANE * 2)            // bytes per plane

typedef unsigned int uint32;

// ---------------- device scratch (no allocations allowed) ----------------
// Packed B fragments for mma.m16n8k16: [variant][ (kt*32+nt)*32 + lane ] -> uint2 (b0,b1)
// variants: 0 = W1 fwd, 1 = W2 fwd, 2 = W2^T bwd, 3 = W1^T bwd
__device__ uint2 g_WpHi[4][16 * 32 * 32];
__device__ uint2 g_WpLo[4][16 * 32 * 32];
__device__ float g_W0T[256 * 12];      // [j][k], k padded 11->12 (fp32, for grad_rq)

__device__ __forceinline__ uint32 bfpair(float a, float b) {
    __nv_bfloat162 p;
    p.x = __float2bfloat16(a);
    p.y = __float2bfloat16(b);
    return *reinterpret_cast<uint32*>(&p);
}
__device__ __forceinline__ float bf_hi(float w) {
    return __bfloat162float(__float2bfloat16(w));
}

__global__ void w0t_kernel(const float* __restrict__ W0) {
    int i = blockIdx.x, j = threadIdx.x;
    if (i < 11)  g_W0T[j * 12 + i] = W0[i * 256 + j];
    if (i == 11) g_W0T[j * 12 + 11] = 0.0f;
}

// Pack weight fragments (hi/lo split). grid (512, 4), block 32.
__global__ void packB_kernel(const float* __restrict__ W1,
                             const float* __restrict__ W2) {
    int bx = blockIdx.x;               // 0..511
    int v  = blockIdx.y;               // variant
    int kt = bx >> 5, nt = bx & 31;
    int lane = threadIdx.x;
    int g = lane >> 2, tig = lane & 3;
    int n = nt * 8 + g;
    int k0 = kt * 16 + 2 * tig;

    const float* W = (v == 0 || v == 3) ? W1 : W2;
    bool trans = (v >= 2);
    float w[4];
#pragma unroll
    for (int i = 0; i < 4; i++) {
        int k = k0 + ((i >> 1) ? 8 : 0) + (i & 1);   // k0, k0+1, k0+8, k0+9
        w[i] = trans ? W[n * 256 + k] : W[k * 256 + n];
    }
    float hi[4], lo[4];
#pragma unroll
    for (int i = 0; i < 4; i++) { hi[i] = bf_hi(w[i]); lo[i] = w[i] - hi[i]; }

    int idx = (kt * 32 + nt) * 32 + lane;
    g_WpHi[v][idx] = make_uint2(bfpair(hi[0], hi[1]), bfpair(hi[2], hi[3]));
    g_WpLo[v][idx] = make_uint2(bfpair(lo[0], lo[1]), bfpair(lo[2], lo[3]));
}

// accurate-enough tanh: 2 MUFU (EX2 + RCP), abs err ~1e-7
__device__ __forceinline__ float tanh_fast(float x) {
    float xc = fminf(fmaxf(x, -15.0f), 15.0f);
    float e  = __expf(2.0f * xc);
    return __fdividef(e - 1.0f, e + 1.0f);
}

__device__ __forceinline__ uint32 smem_u32(const void* p) {
    uint32 a;
    asm("{ .reg .u64 t; cvta.to.shared.u64 t, %1; cvt.u32.u64 %0, t; }"
        : "=r"(a) : "l"(p));
    return a;
}

__device__ __forceinline__ void ldm4(uint32& r0, uint32& r1, uint32& r2, uint32& r3,
                                     uint32 addr) {
    asm volatile("ldmatrix.sync.aligned.m8n8.x4.shared.b16 {%0,%1,%2,%3}, [%4];"
                 : "=r"(r0), "=r"(r1), "=r"(r2), "=r"(r3) : "r"(addr));
}

__device__ __forceinline__ void mma_bf16(float* c, const uint32* a, uint32 b0, uint32 b1) {
    asm volatile(
        "mma.sync.aligned.m16n8k16.row.col.f32.bf16.bf16.f32 "
        "{%0,%1,%2,%3},{%4,%5,%6,%7},{%8,%9},{%0,%1,%2,%3};"
        : "+f"(c[0]), "+f"(c[1]), "+f"(c[2]), "+f"(c[3])
        : "r"(a[0]), "r"(a[1]), "r"(a[2]), "r"(a[3]), "r"(b0), "r"(b1));
}

#define M_TANH 0
#define M_D3   1
#define M_BWD  2

// D[32,256] = A[32,256] @ B[256,256] via bf16 split (Ahi*Bhi + Ahi*Blo + Alo*Bhi).
// 8 warps: warp wy owns cols [wy*32, wy*32+32) = 4 n-tiles; 2 m-tiles; 16 k-tiles.
template <int MODE>
__device__ __forceinline__ void gemm_tc(const uint2* __restrict__ Bhi,
                                        const uint2* __restrict__ Blo,
                                        const float* __restrict__ bias,
                                        const float* __restrict__ w3,
                                        uint32 aHiAddr, uint32 aLoAddr,
                                        __nv_bfloat16* outHi, __nv_bfloat16* outLo,
                                        int tid) {
    const int wy = tid >> 5, lane = tid & 31;
    const int g = lane >> 2, tig = lane & 3;
    const int rr = lane & 15;                  // ldmatrix row within m16
    const int khalf = (lane >> 4) * 8;         // ldmatrix k-half select

    float acc[2][4][4];
#pragma unroll
    for (int mt = 0; mt < 2; mt++)
#pragma unroll
        for (int nt = 0; nt < 4; nt++)
#pragma unroll
            for (int i = 0; i < 4; i++) acc[mt][nt][i] = 0.0f;

    // per-mt ldmatrix byte offsets (k part added per kt)
    uint32 aoff[2];
#pragma unroll
    for (int mt = 0; mt < 2; mt++)
        aoff[mt] = (uint32)(((mt * 16 + rr) * PROW + khalf) * 2);

#pragma unroll 1
    for (int kt = 0; kt < 16; kt++) {
        uint32 kb = (uint32)(kt * 16 * 2);     // k byte offset
        uint32 ah[2][4], al[2][4];
#pragma unroll
        for (int mt = 0; mt < 2; mt++) {
            ldm4(ah[mt][0], ah[mt][1], ah[mt][2], ah[mt][3], aHiAddr + aoff[mt] + kb);
            ldm4(al[mt][0], al[mt][1], al[mt][2], al[mt][3], aLoAddr + aoff[mt] + kb);
        }
        uint2 bh[4], bl[4];
#pragma unroll
        for (int nt = 0; nt < 4; nt++) {
            int idx = (kt * 32 + (wy * 4 + nt)) * 32 + lane;
            bh[nt] = Bhi[idx];
            bl[nt] = Blo[idx];
        }
#pragma unroll
        for (int mt = 0; mt < 2; mt++)
#pragma unroll
            for (int nt = 0; nt < 4; nt++) {
                mma_bf16(acc[mt][nt], ah[mt], bh[nt].x, bh[nt].y);
                mma_bf16(acc[mt][nt], ah[mt], bl[nt].x, bl[nt].y);
                mma_bf16(acc[mt][nt], al[mt], bh[nt].x, bh[nt].y);
            }
    }

    // epilogue: thread owns rows {mt*16+g, +8}, cols {wy*32+nt*8+2tig, +1}
#pragma unroll
    for (int mt = 0; mt < 2; mt++)
#pragma unroll
        for (int nt = 0; nt < 4; nt++) {
            int r0 = mt * 16 + g, r1 = r0 + 8;
            int cb = wy * 32 + nt * 8 + 2 * tig;
            float v00 = acc[mt][nt][0], v01 = acc[mt][nt][1];
            float v10 = acc[mt][nt][2], v11 = acc[mt][nt][3];
            float z00, z01, z10, z11;
            if (MODE == M_TANH || MODE == M_D3) {
                float2 bb = *(const float2*)(bias + cb);
                z00 = tanh_fast(v00 + bb.x); z01 = tanh_fast(v01 + bb.y);
                z10 = tanh_fast(v10 + bb.x); z11 = tanh_fast(v11 + bb.y);
                if (MODE == M_D3) {
                    float2 ww = *(const float2*)(w3 + cb);
                    z00 = ww.x * (1.0f - z00 * z00); z01 = ww.y * (1.0f - z01 * z01);
                    z10 = ww.x * (1.0f - z10 * z10); z11 = ww.y * (1.0f - z11 * z11);
                }
            } else {
                // forward act h = hi + lo at same positions
                __nv_bfloat162 h0h = *(__nv_bfloat162*)(outHi + r0 * PROW + cb);
                __nv_bfloat162 h0l = *(__nv_bfloat162*)(outLo + r0 * PROW + cb);
                __nv_bfloat162 h1h = *(__nv_bfloat162*)(outHi + r1 * PROW + cb);
                __nv_bfloat162 h1l = *(__nv_bfloat162*)(outLo + r1 * PROW + cb);
                float h00 = __bfloat162float(h0h.x) + __bfloat162float(h0l.x);
                float h01 = __bfloat162float(h0h.y) + __bfloat162float(h0l.y);
                float h10 = __bfloat162float(h1h.x) + __bfloat162float(h1l.x);
                float h11 = __bfloat162float(h1h.y) + __bfloat162float(h1l.y);
                z00 = v00 * (1.0f - h00 * h00); z01 = v01 * (1.0f - h01 * h01);
                z10 = v10 * (1.0f - h10 * h10); z11 = v11 * (1.0f - h11 * h11);
            }
            float h00v = bf_hi(z00), h01v = bf_hi(z01);
            float h10v = bf_hi(z10), h11v = bf_hi(z11);
            *(uint32*)(outHi + r0 * PROW + cb) = bfpair(h00v, h01v);
            *(uint32*)(outLo + r0 * PROW + cb) = bfpair(z00 - h00v, z01 - h01v);
            *(uint32*)(outHi + r1 * PROW + cb) = bfpair(h10v, h11v);
            *(uint32*)(outLo + r1 * PROW + cb) = bfpair(z10 - h10v, z11 - h11v);
        }
}

__global__ void __launch_bounds__(NTHREADS, 2) ode_kernel(
    const float* __restrict__ v,  const float* __restrict__ w,
    const float* __restrict__ x,  const float* __restrict__ q,
    const float* __restrict__ W0, const float* __restrict__ b0,
    const float* __restrict__ b1, const float* __restrict__ b2,
    const float* __restrict__ W3,
    float* __restrict__ out) {
    extern __shared__ char sm[];
    __nv_bfloat16* h1hi = (__nv_bfloat16*)(sm);
    __nv_bfloat16* h1lo = (__nv_bfloat16*)(sm + 1 * PLANE_B);
    __nv_bfloat16* h2hi = (__nv_bfloat16*)(sm + 2 * PLANE_B);
    __nv_bfloat16* h2lo = (__nv_bfloat16*)(sm + 3 * PLANE_B);
    __nv_bfloat16* d3hi = (__nv_bfloat16*)(sm + 4 * PLANE_B);
    __nv_bfloat16* d3lo = (__nv_bfloat16*)(sm + 5 * PLANE_B);
    float* rqs = (float*)(sm + 6 * PLANE_B);   // [32][12]
    float* grs = rqs + TILE * 12;              // [32][12]

    const uint32 smb = smem_u32(sm);
    const uint32 a_h1hi = smb, a_h1lo = smb + PLANE_B;
    const uint32 a_h2hi = smb + 2 * PLANE_B, a_h2lo = smb + 3 * PLANE_B;
    const uint32 a_d3hi = smb + 4 * PLANE_B, a_d3lo = smb + 5 * PLANE_B;

    const int tid = threadIdx.x;
    const size_t row0 = (size_t)blockIdx.x * TILE;

    // ---- dxdt = v (pure copy, coalesced) ----
    if (tid < TILE * 6) {
        const size_t base = row0 * 6;
        out[(size_t)12 * Bc + base + tid] = v[base + tid];
    }

    // ---- build rq = [r, qn0, qn1] ----
    if (tid < TILE) {
        int m = tid;
        size_t gg = row0 + m;
        float4 qa = *(const float4*)(q + gg * 8);
        float4 qb = *(const float4*)(q + gg * 8 + 4);
        float n0 = rsqrtf(qa.x * qa.x + qa.y * qa.y + qa.z * qa.z + qa.w * qa.w);
        float n1 = rsqrtf(qb.x * qb.x + qb.y * qb.y + qb.z * qb.z + qb.w * qb.w);
        const float* xp = x + gg * 6;
        float* rp = rqs + m * 12;
        rp[0] = xp[3] - xp[0];
        rp[1] = xp[4] - xp[1];
        rp[2] = xp[5] - xp[2];
        rp[3] = qa.x * n0; rp[4] = qa.y * n0; rp[5] = qa.z * n0; rp[6] = qa.w * n0;
        rp[7] = qb.x * n1; rp[8] = qb.y * n1; rp[9] = qb.z * n1; rp[10] = qb.w * n1;
        rp[11] = 0.0f;
    }
    __syncthreads();

    // ---- layer 0: h1[m][j] = tanh(rq[m] . W0[:,j] + b0[j]); one neuron/thread ----
    {
        int j = tid;
        float wcol[11];
#pragma unroll
        for (int k = 0; k < 11; k++) wcol[k] = W0[k * 256 + j];
        float bb = b0[j];
#pragma unroll 4
        for (int m = 0; m < TILE; m++) {
            const float* rp = rqs + m * 12;
            float zz = bb;
#pragma unroll
            for (int k = 0; k < 11; k++) zz = fmaf(rp[k], wcol[k], zz);
            float z = tanh_fast(zz);
            float zh = bf_hi(z);
            h1hi[m * PROW + j] = __float2bfloat16(zh);
            h1lo[m * PROW + j] = __float2bfloat16(z - zh);
        }
    }
    __syncthreads();

    gemm_tc<M_TANH>(g_WpHi[0], g_WpLo[0], b1, nullptr, a_h1hi, a_h1lo, h2hi, h2lo, tid);
    __syncthreads();
    gemm_tc<M_D3>(g_WpHi[1], g_WpLo[1], b2, W3, a_h2hi, a_h2lo, d3hi, d3lo, tid);
    __syncthreads();
    gemm_tc<M_BWD>(g_WpHi[2], g_WpLo[2], nullptr, nullptr, a_d3hi, a_d3lo, h2hi, h2lo, tid);
    __syncthreads();
    gemm_tc<M_BWD>(g_WpHi[3], g_WpLo[3], nullptr, nullptr, a_h2hi, a_h2lo, h1hi, h1lo, tid);
    __syncthreads();

    // ---- grad_rq[k] = sum_j W0[k][j] * dz1[j] ; 8 threads per row ----
    {
        int m = tid >> 3, kq = tid & 7;
        float a[11];
#pragma unroll
        for (int k = 0; k < 11; k++) a[k] = 0.0f;
        int jb = kq * 32;
#pragma unroll 4
        for (int j = jb; j < jb + 32; j++) {
            float d = __bfloat162float(h1hi[m * PROW + j]) +
                      __bfloat162float(h1lo[m * PROW + j]);
            float4 wA = *(const float4*)(g_W0T + j * 12);
            float4 wB = *(const float4*)(g_W0T + j * 12 + 4);
            float4 wC = *(const float4*)(g_W0T + j * 12 + 8);
            a[0] = fmaf(d, wA.x, a[0]); a[1] = fmaf(d, wA.y, a[1]);
            a[2] = fmaf(d, wA.z, a[2]); a[3] = fmaf(d, wA.w, a[3]);
            a[4] = fmaf(d, wB.x, a[4]); a[5] = fmaf(d, wB.y, a[5]);
            a[6] = fmaf(d, wB.z, a[6]); a[7] = fmaf(d, wB.w, a[7]);
            a[8] = fmaf(d, wC.x, a[8]); a[9] = fmaf(d, wC.y, a[9]);
            a[10] = fmaf(d, wC.z, a[10]);
        }
#pragma unroll
        for (int k = 0; k < 11; k++) {
            a[k] += __shfl_xor_sync(0xffffffffu, a[k], 1);
            a[k] += __shfl_xor_sync(0xffffffffu, a[k], 2);
            a[k] += __shfl_xor_sync(0xffffffffu, a[k], 4);
        }
        if (kq == 0) {
#pragma unroll
            for (int k = 0; k < 11; k++) grs[m * 12 + k] = a[k];
        }
    }
    __syncthreads();

    // ---- epilogue: quaternion dynamics + outputs (one thread per (row, particle)) ----
    if (tid < TILE * 2) {
        int m = tid >> 1, p = tid & 1;
        size_t gg = row0 + m;
        size_t e = gg * 2 + p;
        const float* rp = rqs + m * 12;
        const float* gp = grs + m * 12;
        float q0 = rp[3 + 4 * p], q1 = rp[4 + 4 * p], q2 = rp[5 + 4 * p], q3 = rp[6 + 4 * p];
        float gq0 = gp[3 + 4 * p], gq1 = gp[4 + 4 * p], gq2 = gp[5 + 4 * p], gq3 = gp[6 + 4 * p];
        float wx = w[e * 3 + 0], wy = w[e * 3 + 1], wz = w[e * 3 + 2];

        float dq0 = -0.5f * (q1 * wx + q2 * wy + q3 * wz);
        float dq1 =  0.5f * (q0 * wx + q2 * wz - q3 * wy);
        float dq2 =  0.5f * (q0 * wy - q1 * wz + q3 * wx);
        float dq3 =  0.5f * (q0 * wz + q1 * wy - q2 * wx);
        out[(size_t)18 * Bc + e * 4 + 0] = dq0;
        out[(size_t)18 * Bc + e * 4 + 1] = dq1;
        out[(size_t)18 * Bc + e * 4 + 2] = dq2;
        out[(size_t)18 * Bc + e * 4 + 3] = dq3;

        float Gq[3][4] = {{-q1,  q0,  q3, -q2},
                          {-q2, -q3,  q0,  q1},
                          {-q3,  q2, -q1,  q0}};
        float Gd[3][4] = {{-dq1,  dq0,  dq3, -dq2},
                          {-dq2, -dq3,  dq0,  dq1},
                          {-dq3,  dq2, -dq1,  dq0}};
        float l0 = wx * 1.0f, l1 = wy * 2.0f, l2 = wz * 3.0f;
        float gqv[4] = {gq0, gq1, gq2, gq3};
#pragma unroll
        for (int i = 0; i < 3; i++) {
            float O0 = 2.0f * (Gq[i][0] * Gd[0][0] + Gq[i][1] * Gd[0][1] + Gq[i][2] * Gd[0][2] + Gq[i][3] * Gd[0][3]);
            float O1 = 2.0f * (Gq[i][0] * Gd[1][0] + Gq[i][1] * Gd[1][1] + Gq[i][2] * Gd[1][2] + Gq[i][3] * Gd[1][3]);
            float O2 = 2.0f * (Gq[i][0] * Gd[2][0] + Gq[i][1] * Gd[2][1] + Gq[i][2] * Gd[2][2] + Gq[i][3] * Gd[2][3]);
            float t = -(O0 * l0 + O1 * l1 + O2 * l2)
                      - 0.5f * (Gq[i][0] * gqv[0] + Gq[i][1] * gqv[1] + Gq[i][2] * gqv[2] + Gq[i][3] * gqv[3]);
            out[(size_t)6 * Bc + e * 3 + i] = t / (float)(i + 1);
        }

        float r0 = rp[0], r1 = rp[1], r2 = rp[2];
        float rn = sqrtf(r0 * r0 + r1 * r1 + r2 * r2);
        float coef = 100.0f * (rn - 1.0f) / rn;
        float sgn = p ? -1.0f : 1.0f;
        out[e * 3 + 0] = sgn * (gp[0] + coef * r0) / 7.0f;
        out[e * 3 + 1] = sgn * (gp[1] + coef * r1) / 7.0f;
        out[e * 3 + 2] = sgn * (gp[2] + coef * r2) / 7.0f;
    }
}

extern "C" void kernel_launch(void* const* d_in, const int* in_sizes, int n_in,
                              void* d_out, int out_size) {
    const float* v  = (const float*)d_in[0];
    const float* w  = (const float*)d_in[1];
    const float* x  = (const float*)d_in[2];
    const float* q  = (const float*)d_in[3];
    const float* W0 = (const float*)d_in[4];
    const float* b0 = (const float*)d_in[5];
    const float* W1 = (const float*)d_in[6];
    const float* b1 = (const float*)d_in[7];
    const float* W2 = (const float*)d_in[8];
    const float* b2 = (const float*)d_in[9];
    const float* W3 = (const float*)d_in[10];
    float* out = (float*)d_out;

    constexpr size_t SMEM_BYTES = (size_t)6 * PLANE_B + 2 * TILE * 12 * sizeof(float);
    cudaFuncSetAttribute(ode_kernel, cudaFuncAttributeMaxDynamicSharedMemorySize,
                         (int)SMEM_BYTES);

    w0t_kernel<<<12, 256>>>(W0);
    packB_kernel<<<dim3(512, 4), 32>>>(W1, W2);
    ode_kernel<<<Bc / TILE, NTHREADS, SMEM_BYTES>>>(v, w, x, q, W0, b0,
                                                    b1, b2, W3, out);
}